// round 2
// baseline (speedup 1.0000x reference)
#include <cuda_runtime.h>
#include <math_constants.h>

#define BATCH 16
#define HEADS 8
#define SEQ   1024
#define DIM   64

#define QB 32          // q rows per block
#define KT 64          // k rows per tile
#define SQ_STRIDE  132
#define SKT_STRIDE 66
#define SV_STRIDE  132
#define SPS_STRIDE 66

#define SMEM_FLOATS (QB*SQ_STRIDE + 128*SKT_STRIDE + KT*SV_STRIDE + QB*SPS_STRIDE)
#define SMEM_BYTES  (SMEM_FLOATS * 4)

// scratch (no cudaMalloc allowed)
__device__ int g_i0[BATCH*SEQ];
__device__ int g_i1[BATCH*SEQ];
__device__ int g_list[BATCH*2*SEQ];
__device__ int g_cnt[BATCH*2];

__global__ void init_kernel() {
    int t = threadIdx.x;
    if (t < BATCH*2) g_cnt[t] = 0;
}

// One block per (b, s): exact IoU argmax (first-tie), pair selection, group compaction.
// All arithmetic replicates XLA fp32: each mul/add/sub/div single-rounded (no FMA fusion).
__global__ __launch_bounds__(256) void pairs_kernel(const float* __restrict__ centers) {
    int bs = blockIdx.x;
    int b = bs >> 10;
    int s = bs & 1023;
    const float4* cp = (const float4*)centers;
    float4 bb = cp[bs];
    // box = (cx - w/2, cy - h/2, cx + w/2, cy + h/2); centers = (cx, cy, h, w)
    float x1 = bb.x - 0.5f*bb.w;
    float y1 = bb.y - 0.5f*bb.z;
    float x2 = bb.x + 0.5f*bb.w;
    float y2 = bb.y + 0.5f*bb.z;
    float areas = __fmul_rn(__fsub_rn(x2,x1), __fsub_rn(y2,y1));

    float best = -CUDART_INF_F;
    int bidx = 0;
    for (int k = threadIdx.x; k < SEQ; k += 256) {
        float4 cb = cp[(b<<10)+k];
        float kx1 = cb.x - 0.5f*cb.w;
        float ky1 = cb.y - 0.5f*cb.z;
        float kx2 = cb.x + 0.5f*cb.w;
        float ky2 = cb.y + 0.5f*cb.z;
        float iw = __fsub_rn(fminf(x2,kx2), fmaxf(x1,kx1));
        float ih = __fsub_rn(fminf(y2,ky2), fmaxf(y1,ky1));
        float inter = __fmul_rn(iw, ih);                 // NOTE: no clamp, matches ref
        float ka = __fmul_rn(__fsub_rn(kx2,kx1), __fsub_rn(ky2,ky1));
        float uni = __fsub_rn(__fadd_rn(areas, ka), inter);
        float iou = __fdiv_rn(inter, uni);
        if (k == s) iou = __fsub_rn(iou, 1.0f);
        if (iou > best) { best = iou; bidx = k; }        // strict > keeps first index
    }
    __shared__ float sv[256];
    __shared__ int   si[256];
    int t = threadIdx.x;
    sv[t] = best; si[t] = bidx;
    __syncthreads();
    for (int off = 128; off > 0; off >>= 1) {
        if (t < off) {
            float v2 = sv[t+off]; int i2 = si[t+off];
            if (v2 > sv[t] || (v2 == sv[t] && i2 < si[t])) { sv[t] = v2; si[t] = i2; }
        }
        __syncthreads();
    }
    if (t == 0) {
        int p = si[0];
        float l1s = __fadd_rn(fabsf(__fsub_rn(x2,x1)), fabsf(__fsub_rn(y2,y1)));
        float4 pb = cp[(b<<10)+p];
        float px1 = pb.x - 0.5f*pb.w;
        float py1 = pb.y - 0.5f*pb.z;
        float px2 = pb.x + 0.5f*pb.w;
        float py2 = pb.y + 0.5f*pb.z;
        float l1p = __fadd_rn(fabsf(__fsub_rn(px2,px1)), fabsf(__fsub_rn(py2,py1)));
        bool keep0 = (l1s >= l1p);
        g_i0[bs] = keep0 ? s : p;
        g_i1[bs] = keep0 ? p : s;
        int g = keep0 ? 0 : 1;
        int slot = atomicAdd(&g_cnt[b*2 + g], 1);
        g_list[(b*2 + g)*SEQ + slot] = s;
    }
}

// Flash attention over gathered concatenated rows (effective head-dim 128).
// Block: (q-tile of 32 compacted rows, head h, batch b). 128 threads = 4 warps x 8 q-rows.
__global__ __launch_bounds__(128) void attn_kernel(
    const float* __restrict__ Q, const float* __restrict__ K,
    const float* __restrict__ V, float* __restrict__ out)
{
    int b = blockIdx.z, h = blockIdx.y;
    int g = h >> 2, hh = h & 3;
    int cnt = g_cnt[b*2 + g];
    int tile0 = blockIdx.x * QB;
    if (tile0 >= cnt) return;

    extern __shared__ float smem[];
    float* sQ  = smem;                       // [32][132]  Qcat rows (broadcast reads)
    float* sKT = sQ  + QB*SQ_STRIDE;         // [128][66]  Kcat transposed (c-major)
    float* sV  = sKT + 128*SKT_STRIDE;       // [64][132]  Vcat rows
    float* sPs = sV  + KT*SV_STRIDE;         // [32][66]   staged probabilities

    int t = threadIdx.x;
    int lane = t & 31, warp = t >> 5;
    const int* listp = g_list + (b*2 + g)*SEQ;
    const int* i0p = g_i0 + b*SEQ;
    const int* i1p = g_i1 + b*SEQ;
    size_t headbase = ((size_t)(b*HEADS + h)) * SEQ * DIM;

    // ---- load Q tile (gathered, concatenated) ----
    {
        int rr = t >> 2, chunk = t & 3;               // 32 rows x 4 col-chunks of 32
        int idx = tile0 + rr; if (idx >= cnt) idx = cnt - 1;
        int q = listp[idx];
        int src = (chunk < 2) ? i0p[q] : i1p[q];
        const float4* qp = (const float4*)(Q + headbase + (size_t)src*DIM + (size_t)((chunk & 1)*32));
        float* dst = sQ + rr*SQ_STRIDE + chunk*32;
        #pragma unroll
        for (int j = 0; j < 8; j++) {
            float4 v = qp[j];
            *(float4*)(dst + 4*j) = v;
        }
    }

    float2 s8[8];
    float4 oo[8];
    float mrow[8], lrow[8];
    #pragma unroll
    for (int r = 0; r < 8; r++) {
        oo[r] = make_float4(0.f,0.f,0.f,0.f);
        mrow[r] = -CUDART_INF_F;
        lrow[r] = 0.f;
    }

    for (int kt = 0; kt < SEQ/KT; kt++) {
        __syncthreads();   // prior PV done with sV/sKT; also covers initial sQ fill
        // ---- fill K^T and V tiles (gathered, concatenated) ----
        {
            int kk = t & 63, half = t >> 6;
            int k = kt*KT + kk;
            int src = half ? i1p[k] : i0p[k];
            const float4* kp = (const float4*)(K + headbase + (size_t)src*DIM);
            const float4* vp = (const float4*)(V + headbase + (size_t)src*DIM);
            int cbase = half*64;
            #pragma unroll
            for (int j = 0; j < 16; j++) {
                float4 v = kp[j];
                int c = cbase + 4*j;
                sKT[(c+0)*SKT_STRIDE + kk] = v.x;
                sKT[(c+1)*SKT_STRIDE + kk] = v.y;
                sKT[(c+2)*SKT_STRIDE + kk] = v.z;
                sKT[(c+3)*SKT_STRIDE + kk] = v.w;
            }
            #pragma unroll
            for (int j = 0; j < 16; j++) {
                float4 v = vp[j];
                *(float4*)(sV + kk*SV_STRIDE + cbase + 4*j) = v;
            }
        }
        __syncthreads();

        // ---- scores: 8 q-rows x 64 k (k' = 2*lane, 2*lane+1) ----
        #pragma unroll
        for (int r = 0; r < 8; r++) s8[r] = make_float2(0.f, 0.f);
        {
            const float* kcol = sKT + 2*lane;
            const float* qrow = sQ + warp*8*SQ_STRIDE;
            #pragma unroll 4
            for (int c = 0; c < 128; c += 2) {
                float2 ka = *(const float2*)(kcol + c*SKT_STRIDE);
                float2 kb = *(const float2*)(kcol + (c+1)*SKT_STRIDE);
                #pragma unroll
                for (int r = 0; r < 8; r++) {
                    float2 q = *(const float2*)(qrow + r*SQ_STRIDE + c);
                    s8[r].x += q.x*ka.x; s8[r].x += q.y*kb.x;
                    s8[r].y += q.x*ka.y; s8[r].y += q.y*kb.y;
                }
            }
        }

        // ---- online softmax + stage P ----
        #pragma unroll
        for (int r = 0; r < 8; r++) {
            float mt = fmaxf(s8[r].x, s8[r].y);
            #pragma unroll
            for (int off = 16; off > 0; off >>= 1)
                mt = fmaxf(mt, __shfl_xor_sync(0xffffffffu, mt, off));
            float mn = fmaxf(mrow[r], mt);
            float corr = __expf(mrow[r] - mn);     // -inf - finite -> exp = 0 (first tile)
            float p0 = __expf(s8[r].x - mn);
            float p1 = __expf(s8[r].y - mn);
            float lt = p0 + p1;
            #pragma unroll
            for (int off = 16; off > 0; off >>= 1)
                lt += __shfl_xor_sync(0xffffffffu, lt, off);
            lrow[r] = lrow[r]*corr + lt;
            mrow[r] = mn;
            oo[r].x *= corr; oo[r].y *= corr; oo[r].z *= corr; oo[r].w *= corr;
            *(float2*)(sPs + (warp*8 + r)*SPS_STRIDE + 2*lane) = make_float2(p0, p1);
        }
        __syncwarp();   // sPs rows are warp-private; warp-level ordering suffices

        // ---- PV: lane owns output cols 4*lane..4*lane+3 ----
        {
            const float* vbase = sV + 4*lane;
            const float* pbase = sPs + warp*8*SPS_STRIDE;
            #pragma unroll 4
            for (int k = 0; k < KT; k++) {
                float4 v = *(const float4*)(vbase + k*SV_STRIDE);
                #pragma unroll
                for (int r = 0; r < 8; r++) {
                    float p = pbase[r*SPS_STRIDE + k];   // broadcast
                    oo[r].x += p*v.x; oo[r].y += p*v.y;
                    oo[r].z += p*v.z; oo[r].w += p*v.w;
                }
            }
        }
    }

    // ---- epilogue: normalize, scale by 1/sqrt(2D), scatter to output row ----
    #pragma unroll
    for (int r = 0; r < 8; r++) {
        int idx = tile0 + warp*8 + r;
        if (idx < cnt) {
            int q = listp[idx];
            float inv = (1.0f / lrow[r]) * 0.08838834764831845f;  // 1/sqrt(128)
            float4 ov = make_float4(oo[r].x*inv, oo[r].y*inv, oo[r].z*inv, oo[r].w*inv);
            *(float4*)(out + ((size_t)(b*SEQ + q))*512 + hh*128 + 4*lane) = ov;
        }
    }
}

extern "C" void kernel_launch(void* const* d_in, const int* in_sizes, int n_in,
                              void* d_out, int out_size) {
    const float* Q = (const float*)d_in[0];
    const float* K = (const float*)d_in[1];
    const float* V = (const float*)d_in[2];
    const float* C = (const float*)d_in[3];
    float* out = (float*)d_out;

    // idempotent, host-side only (not replayed by the graph)
    cudaFuncSetAttribute(attn_kernel, cudaFuncAttributeMaxDynamicSharedMemorySize, SMEM_BYTES);

    init_kernel<<<1, 32>>>();
    pairs_kernel<<<BATCH*SEQ, 256>>>(C);
    attn_kernel<<<dim3(SEQ/QB, HEADS, BATCH), 128, SMEM_BYTES>>>(Q, K, V, out);
}